// round 9
// baseline (speedup 1.0000x reference)
#include <cuda_runtime.h>
#include <cuda_bf16.h>
#include <math_constants.h>

#define B 128
#define P 8732
#define C 21
#define NEG_POS_RATIO 3
#define TILE_A 256                    // anchors per stream block
#define NT_A 256
#define NBLK_ROW ((P + TILE_A - 1) / TILE_A)   // 35
#define NT_B 1024
#define KPT 9                         // ceil(8732/1024)

__device__ unsigned g_keys[(size_t)B * P];   // 4.47 MB radix keys
__device__ float    g_rowf[B][4];            // per-row: pos_conf, reg, mask_sum (3 used)
__device__ int      g_rowi[B];               // per-row num_pos
__device__ float    g_acc[4];                // global: pos, reg, mask, neg
__device__ int      g_done;

__device__ __forceinline__ unsigned f2key(float f) {
    unsigned b = __float_as_uint(f);
    return (b & 0x80000000u) ? ~b : (b | 0x80000000u);
}
__device__ __forceinline__ float key2f(unsigned k) {
    unsigned b = (k & 0x80000000u) ? (k & 0x7FFFFFFFu) : ~k;
    return __uint_as_float(b);
}
__device__ __forceinline__ float warp_sum_f(float v) {
    #pragma unroll
    for (int o = 16; o > 0; o >>= 1) v += __shfl_down_sync(0xFFFFFFFFu, v, o);
    return v;
}
__device__ __forceinline__ unsigned smem_u32(const void* p) {
    return (unsigned)__cvta_generic_to_shared(p);
}

// ================= kernel A: streaming (grid 35 x 128, 256 thr) =================
__global__ void k_stream(const float* __restrict__ conf,
                         const float* __restrict__ pred,
                         const int*   __restrict__ labels,
                         const float* __restrict__ gt,
                         const float* __restrict__ mask) {
    __shared__ float sc[TILE_A * C];          // 21504 B
    __shared__ float sredf[3][8];
    __shared__ int   sredi[8];

    const int b  = blockIdx.y;
    const int p0 = blockIdx.x * TILE_A;
    const int t  = threadIdx.x;
    const int wid = t >> 5, lane = t & 31;
    const size_t rb = (size_t)b * P;
    const int nanch = min(TILE_A, P - p0);
    const int nf4   = (nanch * C) >> 2;       // 1344 full / 147 tail (both exact)

    // stage conf tile via cp.async (16B aligned: p0*C*4 and row base are mult of 16)
    {
        const unsigned sb = smem_u32(sc);
        const float4* src = (const float4*)(conf + (rb + p0) * C);
        for (int i = t; i < nf4; i += NT_A) {
            asm volatile("cp.async.cg.shared.global [%0], [%1], 16;"
                         :: "r"(sb + i * 16), "l"(src + i));
        }
        asm volatile("cp.async.commit_group;");
    }
    // overlap: labels/mask
    int lab = 0; float mk = 0.0f;
    if (t < nanch) { lab = labels[rb + p0 + t]; mk = mask[rb + p0 + t]; }
    asm volatile("cp.async.wait_group 0;");
    __syncthreads();

    float posc = 0.0f, regl = 0.0f, msum = 0.0f;
    int   npos = 0;

    if (t < nanch) {
        const float* c = sc + t * C;          // stride 21: conflict-free
        float v[C];
        #pragma unroll
        for (int j = 0; j < C; j++) v[j] = c[j];

        float m = v[0];
        #pragma unroll
        for (int j = 1; j < C; j++) m = fmaxf(m, v[j]);
        // 3-way split sum to break the serial FADD chain
        float s0 = 0.0f, s1 = 0.0f, s2 = 0.0f;
        #pragma unroll
        for (int j = 0; j < C; j += 3) s0 += __expf(v[j] - m);
        #pragma unroll
        for (int j = 1; j < C; j += 3) s1 += __expf(v[j] - m);
        #pragma unroll
        for (int j = 2; j < C; j += 3) s2 += __expf(v[j] - m);
        const float lse = __logf(s0 + s1 + s2) + m;

        msum = mk;
        unsigned key = 0u;
        if (lab > 0) {
            npos = 1;
            float clab = v[0];
            #pragma unroll
            for (int j = 1; j < C; j++) clab = (lab == j) ? v[j] : clab;
            posc = mk * (lse - clab);
            const size_t gi = rb + p0 + t;
            const float4 pv = *(const float4*)(pred + gi * 4);
            const float4 gv = *(const float4*)(gt   + gi * 4);
            float r = 0.0f, d, ad;
            d = pv.x - gv.x; ad = fabsf(d); r += (ad < 1.0f) ? 0.5f * d * d : ad - 0.5f;
            d = pv.y - gv.y; ad = fabsf(d); r += (ad < 1.0f) ? 0.5f * d * d : ad - 0.5f;
            d = pv.z - gv.z; ad = fabsf(d); r += (ad < 1.0f) ? 0.5f * d * d : ad - 0.5f;
            d = pv.w - gv.w; ad = fabsf(d); r += (ad < 1.0f) ? 0.5f * d * d : ad - 0.5f;
            regl = mk * r;
        } else {
            key = f2key(lse - v[0]);          // bg loss >= 0 -> nonzero key
        }
        g_keys[rb + p0 + t] = key;
    }

    // block reduce (8 warps) -> per-row atomics (35 writers per address)
    posc = warp_sum_f(posc);
    regl = warp_sum_f(regl);
    msum = warp_sum_f(msum);
    npos = __reduce_add_sync(0xFFFFFFFFu, npos);
    if (lane == 0) { sredf[0][wid] = posc; sredf[1][wid] = regl; sredf[2][wid] = msum; sredi[wid] = npos; }
    __syncthreads();
    if (t == 0) {
        float a0 = 0, a1 = 0, a2 = 0; int a3 = 0;
        #pragma unroll
        for (int w = 0; w < 8; w++) { a0 += sredf[0][w]; a1 += sredf[1][w]; a2 += sredf[2][w]; a3 += sredi[w]; }
        if (a0 != 0.0f) atomicAdd(&g_rowf[b][0], a0);
        if (a1 != 0.0f) atomicAdd(&g_rowf[b][1], a1);
        atomicAdd(&g_rowf[b][2], a2);
        if (a3) atomicAdd(&g_rowi[b], a3);
    }
}

// ================= kernel B: per-row exact top-k sum + finalize =================
__global__ __launch_bounds__(NT_B, 1)
void k_select(float* __restrict__ out) {
    const int b    = blockIdx.x;
    const int t    = threadIdx.x;
    const int wid  = t >> 5;
    const int lane = t & 31;

    __shared__ float    sredf[32];
    __shared__ unsigned sredu[32];
    __shared__ int      sredi[32];
    __shared__ unsigned scnt12;
    __shared__ int      scnt3;
    __shared__ int      sk;
    __shared__ bool     sLast;

    const size_t rb = (size_t)b * P;

    // load this row's keys (coalesced)
    unsigned keys[KPT];
    #pragma unroll
    for (int i = 0; i < KPT; i++) {
        const int idx = t + i * NT_B;
        keys[i] = (idx < P) ? g_keys[rb + idx] : 0u;
    }
    if (t == 0) sk = g_rowi[b] * NEG_POS_RATIO;
    __syncthreads();
    const int k = sk;

    float negsum = 0.0f;
    if (k > 0) {
        unsigned prefix = 0u;
        for (int bit = 30; bit >= 0; bit -= 2) {
            const unsigned c1 = prefix | (1u << bit);
            const unsigned c2 = prefix | (2u << bit);
            const unsigned c3 = prefix | (3u << bit);
            unsigned p12 = 0; int n3 = 0;
            #pragma unroll
            for (int i = 0; i < KPT; i++) {
                p12 += (keys[i] >= c1) + ((unsigned)(keys[i] >= c2) << 16);
                n3  += (keys[i] >= c3);
            }
            p12 = __reduce_add_sync(0xFFFFFFFFu, p12);
            n3  = __reduce_add_sync(0xFFFFFFFFu, n3);
            if (lane == 0) { sredu[wid] = p12; sredi[wid] = n3; }
            __syncthreads();
            if (wid == 0) {
                unsigned u = __reduce_add_sync(0xFFFFFFFFu, sredu[lane]);
                int      v = __reduce_add_sync(0xFFFFFFFFu, sredi[lane]);
                if (lane == 0) { scnt12 = u; scnt3 = v; }
            }
            __syncthreads();
            const int n1 = (int)(scnt12 & 0xFFFFu);
            const int n2 = (int)(scnt12 >> 16);
            prefix = (scnt3 >= k) ? c3 : (n2 >= k) ? c2 : (n1 >= k) ? c1 : prefix;
        }

        int cgt = 0; float sgt = 0.0f;
        #pragma unroll
        for (int i = 0; i < KPT; i++) {
            if (keys[i] > prefix) { cgt++; sgt += key2f(keys[i]); }
        }
        cgt = __reduce_add_sync(0xFFFFFFFFu, cgt);
        sgt = warp_sum_f(sgt);
        if (lane == 0) { sredi[wid] = cgt; sredf[wid] = sgt; }
        __syncthreads();
        if (t == 0) {
            int ctot = 0; float stot = 0.0f;
            #pragma unroll
            for (int w = 0; w < 32; w++) { ctot += sredi[w]; stot += sredf[w]; }
            const float tv = (prefix != 0u) ? key2f(prefix) : 0.0f;
            negsum = stot + (float)(k - ctot) * tv;
        }
    }

    // t0: fold this row into global accumulators, then reset row scratch
    if (t == 0) {
        atomicAdd(&g_acc[0], g_rowf[b][0]);
        atomicAdd(&g_acc[1], g_rowf[b][1]);
        atomicAdd(&g_acc[2], g_rowf[b][2]);
        if (negsum != 0.0f) atomicAdd(&g_acc[3], negsum);
        g_rowf[b][0] = 0.0f; g_rowf[b][1] = 0.0f; g_rowf[b][2] = 0.0f;
        g_rowi[b] = 0;
        __threadfence();
        const int prev = atomicAdd(&g_done, 1);
        sLast = (prev == B - 1);
    }
    __syncthreads();
    if (sLast && t == 0) {
        volatile float* a = g_acc;
        const float inv = 1.0f / a[2];
        out[0] = a[1] * inv;
        out[1] = (a[0] + a[3]) * inv;
        a[0] = 0.0f; a[1] = 0.0f; a[2] = 0.0f; a[3] = 0.0f;
        g_done = 0;
    }
}

extern "C" void kernel_launch(void* const* d_in, const int* in_sizes, int n_in,
                              void* d_out, int out_size) {
    const float* conf   = (const float*)d_in[0];
    const float* pred   = (const float*)d_in[1];
    const int*   labels = (const int*)d_in[2];
    const float* gt     = (const float*)d_in[3];
    const float* mask   = (const float*)d_in[4];
    float* out = (float*)d_out;

    dim3 ga(NBLK_ROW, B);
    k_stream<<<ga, NT_A>>>(conf, pred, labels, gt, mask);
    k_select<<<B, NT_B>>>(out);
}